// round 8
// baseline (speedup 1.0000x reference)
#include <cuda_runtime.h>

// CentDif: 6th-order central difference + 2-channel advection combine.
// u: [16384, 2, 2048] fp32. No smem/barriers. Each thread computes outputs
// [8t+4, 8t+12) for TWO consecutive m-rows; all 8 v8 (256-bit) window loads
// are front-batched so each warp issues ~8KB of reads back-to-back before
// any store -> longer read bursts, fewer read/write turnarounds per warp.

#define M_DIM 16384
#define L_DIM 2048
#define IGST  10
#define NTHREADS 256
#define RPC   2          // m-rows per CTA (per-thread ILP)

__device__ __forceinline__ void ldg256(const float* __restrict__ p, float* r) {
    asm volatile(
        "ld.global.nc.v8.f32 {%0,%1,%2,%3,%4,%5,%6,%7}, [%8];"
        : "=f"(r[0]), "=f"(r[1]), "=f"(r[2]), "=f"(r[3]),
          "=f"(r[4]), "=f"(r[5]), "=f"(r[6]), "=f"(r[7])
        : "l"(p));
}

__global__ __launch_bounds__(NTHREADS) void centdif_kernel(
    const float* __restrict__ u, float* __restrict__ out)
{
    const int m0 = blockIdx.x * RPC;
    const int t  = threadIdx.x;

    if (t == NTHREADS - 1) {
        // Ghost ends (l in [0,4) and [2044,2048), both channels, both rows): exactly 0.
        const float4 z = make_float4(0.f, 0.f, 0.f, 0.f);
        #pragma unroll
        for (int r = 0; r < RPC; ++r) {
            const size_t base = (size_t)(m0 + r) * (2 * L_DIM);
            __stcs((float4*)(out + base), z);
            __stcs((float4*)(out + base + L_DIM - 4), z);
            __stcs((float4*)(out + base + L_DIM), z);
            __stcs((float4*)(out + base + 2 * L_DIM - 4), z);
        }
        return;
    }

    const float c = (float)(1.0 / (60.0 * 0.012));  // 1/(60*DX)
    const int l0 = 8 * t + 4;

    // Front-batch ALL window loads for both rows (byte offset 32t: 32B-aligned).
    // win[r][ch][k] = u[m0+r, ch, 8t + k], k = 0..15
    float win[RPC][2][16];
    #pragma unroll
    for (int r = 0; r < RPC; ++r) {
        const size_t base = (size_t)(m0 + r) * (2 * L_DIM);
        const float* w0 = u + base + 8 * t;
        const float* w1 = u + base + L_DIM + 8 * t;
        ldg256(w0,     win[r][0]);
        ldg256(w0 + 8, win[r][0] + 8);
        ldg256(w1,     win[r][1]);
        ldg256(w1 + 8, win[r][1] + 8);
    }

    #pragma unroll
    for (int r = 0; r < RPC; ++r) {
        const float* a = win[r][0];
        const float* b = win[r][1];
        float r0[8], r1[8];
        #pragma unroll
        for (int i = 0; i < 8; ++i) {
            const int l = l0 + i;
            float du0 = 0.0f, du1 = 0.0f;
            if (l >= IGST && l < L_DIM - IGST) {
                // taps: l-3 -> a[i+1] ... l+3 -> a[i+7]; u[l] -> a[i+4]
                du0 = (-a[i+1] + 9.0f*a[i+2] - 45.0f*a[i+3]
                       + 45.0f*a[i+5] - 9.0f*a[i+6] + a[i+7]) * c;
                du1 = (-b[i+1] + 9.0f*b[i+2] - 45.0f*b[i+3]
                       + 45.0f*b[i+5] - 9.0f*b[i+6] + b[i+7]) * c;
            }
            const float uu0 = a[i+4];
            const float uu1 = b[i+4];
            r0[i] = -(uu1 * du0 + uu0 * du1);
            r1[i] = -(2.0f * du0 + uu1 * du1);
        }

        const size_t base = (size_t)(m0 + r) * (2 * L_DIM);
        float4* o0 = (float4*)(out + base + l0);
        float4* o1 = (float4*)(out + base + L_DIM + l0);
        __stcs(o0 + 0, make_float4(r0[0], r0[1], r0[2], r0[3]));
        __stcs(o0 + 1, make_float4(r0[4], r0[5], r0[6], r0[7]));
        __stcs(o1 + 0, make_float4(r1[0], r1[1], r1[2], r1[3]));
        __stcs(o1 + 1, make_float4(r1[4], r1[5], r1[6], r1[7]));
    }
}

extern "C" void kernel_launch(void* const* d_in, const int* in_sizes, int n_in,
                              void* d_out, int out_size)
{
    const float* u = (const float*)d_in[0];
    float* out = (float*)d_out;
    centdif_kernel<<<M_DIM / RPC, NTHREADS>>>(u, out);
}